// round 13
// baseline (speedup 1.0000x reference)
#include <cuda_runtime.h>
#include <cuda_bf16.h>
#include <cstdint>

#define N_TOK   65536
#define DDIM    256
#define KCODE   1024
#define DECAY   0.99f
#define OMD     0.01f
#define EPSV    1e-5f
#define VQ_COMMIT 0.25f
#define TH_RES  0.8f

#define BM 128
#define APITCH 264          // bf16 elems per A smem row (pad for ldmatrix)

// smem byte offsets
#define SM_AH    0
#define A_SZ     (128 * APITCH * 2)                  // 67584
#define SM_ENORM A_SZ                                // 67584
#define SM_CANDV (SM_ENORM + 4096)                   // 71680: [128][8][3] float
#define SM_CANDI (SM_CANDV + 12288)                  // 83968: [128][8][3] int
#define SM_BV    (SM_CANDI + 12288)                  // 96256
#define SM_BI    (SM_BV + 512)                       // 96768
#define SM_FLAGN (SM_BI + 512)                       // 97280
#define SM_FLAGS (SM_FLAGN + 16)                     // 97296
#define SMEM_K1  (SM_FLAGS + 544)                    // 97840

// ---- device scratch ----
__device__ float g_Et[KCODE * DDIM];                 // [code][d] exact fp32
__device__ float g_esum[KCODE * DDIM];
__device__ float g_counts[KCODE];
__device__ float g_enorm[KCODE];
__device__ float g_invcs[KCODE];
__device__ float g_loss;
// B fragment-major, 16B-paired: [c(8)][wn(2)][s(16)][j2(4)][lane(32)] x 16B
__device__ __align__(16) unsigned char g_Bf[8 * 2 * 16 * 4 * 32 * 16];   // 512KB

// ---- PTX helpers ----
__device__ __forceinline__ uint32_t smem_u32(const void* p) {
    uint32_t a;
    asm("{ .reg .u64 t; cvta.to.shared.u64 t, %1; cvt.u32.u64 %0, t; }" : "=r"(a) : "l"(p));
    return a;
}
__device__ __forceinline__ void ldsm_x4(uint32_t* r, uint32_t a) {
    asm volatile("ldmatrix.sync.aligned.m8n8.x4.shared.b16 {%0,%1,%2,%3}, [%4];"
        : "=r"(r[0]), "=r"(r[1]), "=r"(r[2]), "=r"(r[3]) : "r"(a));
}
__device__ __forceinline__ void mma16816(float* d, const uint32_t* a, const uint32_t* b) {
    asm volatile("mma.sync.aligned.m16n8k16.row.col.f32.bf16.bf16.f32 "
        "{%0,%1,%2,%3}, {%4,%5,%6,%7}, {%8,%9}, {%0,%1,%2,%3};"
        : "+f"(d[0]), "+f"(d[1]), "+f"(d[2]), "+f"(d[3])
        : "r"(a[0]), "r"(a[1]), "r"(a[2]), "r"(a[3]), "r"(b[0]), "r"(b[1]));
}
__device__ __forceinline__ uint32_t pack_bf2(float x, float y) {
    __nv_bfloat16 a = __float2bfloat16(x), b = __float2bfloat16(y);
    return ((uint32_t)__bfloat16_as_ushort(b) << 16) | (uint32_t)__bfloat16_as_ushort(a);
}

// Reference-matching fp32 distance: strictly sequential FFMA chain over
// ascending d, then dist = fmaf(-2, dot, enorm).
__device__ __forceinline__ float chain_dist_f32(const float* __restrict__ zr,
                                                const float* __restrict__ er,
                                                float en) {
    float dot = 0.0f;
    #pragma unroll 16
    for (int i = 0; i < DDIM; ++i) {
        dot = fmaf(zr[i], er[i], dot);
    }
    return fmaf(-2.0f, dot, en);
}

// ---------------------------------------------------------------------------
// k0: exact Et [code][d], fragment-major 16B-paired bf16 B image, zero stats
// ---------------------------------------------------------------------------
__global__ void k0_prep(const float* __restrict__ E) {
    int stride = gridDim.x * blockDim.x;
    for (int i = blockIdx.x * blockDim.x + threadIdx.x; i < KCODE * DDIM; i += stride) {
        int k = i >> 8, dd = i & 255;   // code, dim
        float x = E[dd * KCODE + k];
        g_Et[i] = x;
        g_esum[i] = 0.0f;
        if (i < KCODE) g_counts[i] = 0.0f;
        if (i == 0)    g_loss = 0.0f;
        // fragment-major slot for mma.m16n8k16 B operand, (j,j+1) paired in 16B
        int c = k >> 7, nin = k & 127;
        int wn = nin >> 6, j = (nin >> 3) & 7, nrow = nin & 7;
        int s = dd >> 4, kin = dd & 15;
        int r = kin >> 3, kp = kin & 7, q = kp >> 1, bit = kp & 1;
        int l = nrow * 4 + q;
        int off = ((((c * 2 + wn) * 16 + s) * 4 + (j >> 1)) * 32 + l) * 16
                  + (j & 1) * 8 + r * 4 + bit * 2;
        *(__nv_bfloat16*)(g_Bf + off) = __float2bfloat16(x);
    }
}

__global__ void k0_enorm() {
    int gw = (blockIdx.x * blockDim.x + threadIdx.x) >> 5;
    int lane = threadIdx.x & 31;
    if (gw >= KCODE) return;
    const float4* row = (const float4*)(g_Et + (size_t)gw * DDIM);
    float s = 0.f;
    float4 a = row[lane];       s += a.x*a.x + a.y*a.y + a.z*a.z + a.w*a.w;
    float4 b = row[lane + 32];  s += b.x*b.x + b.y*b.y + b.z*b.z + b.w*b.w;
    #pragma unroll
    for (int o = 16; o; o >>= 1) s += __shfl_xor_sync(0xffffffffu, s, o);
    if (lane == 0) g_enorm[gw] = s;
}

// ---------------------------------------------------------------------------
#define UPD3(v, ix, d, n) do { \
    if ((d) < (v)[0] || ((d) == (v)[0] && (n) < (ix)[0])) { \
        (v)[2]=(v)[1]; (ix)[2]=(ix)[1]; (v)[1]=(v)[0]; (ix)[1]=(ix)[0]; (v)[0]=(d); (ix)[0]=(n); \
    } else if ((d) < (v)[1] || ((d) == (v)[1] && (n) < (ix)[1])) { \
        (v)[2]=(v)[1]; (ix)[2]=(ix)[1]; (v)[1]=(d); (ix)[1]=(n); \
    } else if ((d) < (v)[2] || ((d) == (v)[2] && (n) < (ix)[2])) { \
        (v)[2]=(d); (ix)[2]=(n); \
    } } while (0)

// ---------------------------------------------------------------------------
// k1: 16-warp (m16n64 tiles) barrier-free hh HMMA GEMM, B streamed from
//     fragment-major gmem; per-lane top-3 + chain-fp32 rescore + epilogue
// ---------------------------------------------------------------------------
__global__ __launch_bounds__(512)
void k1_main(const float* __restrict__ z, float* __restrict__ out_zq, int blk0) {
    extern __shared__ unsigned char sm[];
    const uint32_t sb = smem_u32(sm);
    float* en_s  = (float*)(sm + SM_ENORM);
    float* candv = (float*)(sm + SM_CANDV);
    int*   candi = (int*)(sm + SM_CANDI);
    float* bv_s  = (float*)(sm + SM_BV);
    int*   bi_s  = (int*)(sm + SM_BI);
    int*   flagn = (int*)(sm + SM_FLAGN);
    int*   flags = (int*)(sm + SM_FLAGS);

    const int tid = threadIdx.x, lane = tid & 31, wid = tid >> 5;
    const int wm = wid >> 1, wn = wid & 1;
    const int row0 = (blk0 + blockIdx.x) * BM;

    if (tid == 0) *flagn = 0;

    // ---- A block load + bf16-hi into smem (8192 float4 / 512 thr) ----
    #pragma unroll 4
    for (int it = 0; it < 16; ++it) {
        int v = tid + it * 512;
        int r = v >> 6, c4 = v & 63;
        float4 x = *(const float4*)(z + (size_t)(row0 + r) * DDIM + c4 * 4);
        uint2 hh;
        hh.x = pack_bf2(x.x, x.y); hh.y = pack_bf2(x.z, x.w);
        *(uint2*)(sm + SM_AH + (size_t)(r * APITCH + c4 * 4) * 2) = hh;
    }
    *(float2*)(en_s + tid * 2) = *(const float2*)(g_enorm + tid * 2);
    __syncthreads();

    const uint32_t aAddr = sb + SM_AH +
        (uint32_t)(((wm * 16 + (lane & 15)) * APITCH + (lane >> 4) * 8) * 2);

    float tv[2][3];
    int   ti[2][3];
    #pragma unroll
    for (int g = 0; g < 2; ++g) { tv[g][0] = tv[g][1] = tv[g][2] = 3.4e38f; ti[g][0] = ti[g][1] = ti[g][2] = 0; }

    for (int c = 0; c < 8; ++c) {
        float acc[8][4];
        #pragma unroll
        for (int j = 0; j < 8; ++j)
            #pragma unroll
            for (int r = 0; r < 4; ++r) acc[j][r] = 0.f;

        const unsigned char* bc = g_Bf + (size_t)((c * 2 + wn) * 16) * 2048 + lane * 16;
        #pragma unroll
        for (int s = 0; s < 16; ++s) {
            // B fragments: 4 independent LDG.128 (each = fragments for j,j+1)
            uint4 bfr[4];
            const uint4* bp = (const uint4*)(bc + s * 2048);
            #pragma unroll
            for (int j2 = 0; j2 < 4; ++j2) bfr[j2] = bp[j2 * 32];
            // A fragment from smem
            uint32_t ah[4];
            ldsm_x4(ah, aAddr + (uint32_t)(s * 32));
            #pragma unroll
            for (int j2 = 0; j2 < 4; ++j2) {
                const uint32_t* bw = (const uint32_t*)&bfr[j2];
                mma16816(acc[2 * j2],     ah, bw);
                mma16816(acc[2 * j2 + 1], ah, bw + 2);
            }
        }

        // fold chunk c into per-lane top-3 (two row-groups)
        const int nb0 = c * 128 + wn * 64 + 2 * (lane & 3);
        #pragma unroll
        for (int j = 0; j < 8; ++j) {
            int n0 = nb0 + j * 8;
            float e0 = en_s[n0], e1 = en_s[n0 + 1];
            float d0 = e0 - 2.0f * acc[j][0];
            float d1 = e1 - 2.0f * acc[j][1];
            float d2 = e0 - 2.0f * acc[j][2];
            float d3 = e1 - 2.0f * acc[j][3];
            UPD3(tv[0], ti[0], d0, n0);
            UPD3(tv[0], ti[0], d1, n0 + 1);
            UPD3(tv[1], ti[1], d2, n0);
            UPD3(tv[1], ti[1], d3, n0 + 1);
        }
    }

    // ---- write per-row candidates (8 disjoint subsets per row) ----
    #pragma unroll
    for (int g = 0; g < 2; ++g) {
        int row = wm * 16 + (lane >> 2) + g * 8;
        int base = (row * 8 + wn * 4 + (lane & 3)) * 3;
        candv[base + 0] = tv[g][0]; candv[base + 1] = tv[g][1]; candv[base + 2] = tv[g][2];
        candi[base + 0] = ti[g][0]; candi[base + 1] = ti[g][1]; candi[base + 2] = ti[g][2];
    }
    __syncthreads();

    // ---- per-row finalize (threads 0..127) ----
    if (tid < 128) {
        const int base = tid * 24;
        float v0 = candv[base]; int i0 = candi[base];
        #pragma unroll
        for (int t = 1; t < 24; ++t) {
            float v = candv[base + t]; int i = candi[base + t];
            if (v < v0 || (v == v0 && i < i0)) { v0 = v; i0 = i; }
        }
        // safety net: min over lanes of each lane's 3rd-best
        float m3 = candv[base + 2];
        #pragma unroll
        for (int L = 1; L < 8; ++L) m3 = fminf(m3, candv[base + L * 3 + 2]);

        // gather candidates within TH of best
        int cl[8]; int cnt = 0;
        #pragma unroll
        for (int t = 0; t < 24; ++t) {
            if (candv[base + t] < v0 + TH_RES) {
                if (cnt < 8) cl[cnt] = candi[base + t];
                ++cnt;
            }
        }

        if (m3 < v0 + TH_RES || cnt > 8) {
            int s = atomicAdd(flagn, 1);
            flags[s] = tid;                      // full chain-fp32 rescan later
            bv_s[tid] = v0; bi_s[tid] = i0;      // placeholder (overwritten)
        } else if (cnt <= 1) {
            bv_s[tid] = v0; bi_s[tid] = i0;
        } else {
            const float* zr = z + (size_t)(row0 + tid) * DDIM;
            float bd = 3.4e38f; int bk = 0x7fffffff;
            for (int t = 0; t < cnt; ++t) {
                int k = cl[t];
                float d = chain_dist_f32(zr, g_Et + (size_t)k * DDIM, en_s[k]);
                if (d < bd || (d == bd && k < bk)) { bd = d; bk = k; }
            }
            bv_s[tid] = bd; bi_s[tid] = bk;
        }
    }
    __syncthreads();

    // ---- rare full chain-fp32 rescan (warp-cooperative) ----
    int nf = *flagn;
    for (int f = wid; f < nf; f += 16) {
        int row = flags[f];
        const float* zr = z + (size_t)(row0 + row) * DDIM;
        float bd = 3.4e38f; int bk = 0x7fffffff;
        for (int k = lane; k < KCODE; k += 32) {
            float d = chain_dist_f32(zr, g_Et + (size_t)k * DDIM, en_s[k]);
            if (d < bd) { bd = d; bk = k; }
        }
        #pragma unroll
        for (int o = 16; o; o >>= 1) {
            float ov = __shfl_xor_sync(0xffffffffu, bd, o);
            int   ok = __shfl_xor_sync(0xffffffffu, bk, o);
            if (ov < bd || (ov == bd && ok < bk)) { bd = ov; bk = ok; }
        }
        if (lane == 0) { bv_s[row] = bd; bi_s[row] = bk; }
    }
    __syncthreads();

    // ---- fused epilogue: 16 warps x 8 rows ----
    float lossacc = 0.f;
    #pragma unroll
    for (int rr = 0; rr < 8; ++rr) {
        int r = wid * 8 + rr;
        int R = row0 + r;
        int k = bi_s[r];
        const float4* zrow = (const float4*)(z + (size_t)R * DDIM);
        float4*       orow = (float4*)(out_zq + (size_t)R * DDIM);
        const float4* et   = (const float4*)(g_Et + (size_t)k * DDIM);
        float zsq = 0.f;
        #pragma unroll
        for (int itc = 0; itc < 2; ++itc) {
            int cidx = lane + itc * 32;
            float4 zv = zrow[cidx];
            zsq += zv.x * zv.x + zv.y * zv.y + zv.z * zv.z + zv.w * zv.w;
            float* es = g_esum + (size_t)k * DDIM + cidx * 4;
            atomicAdd(es + 0, zv.x);
            atomicAdd(es + 1, zv.y);
            atomicAdd(es + 2, zv.z);
            atomicAdd(es + 3, zv.w);
            orow[cidx] = et[cidx];
        }
        #pragma unroll
        for (int o = 16; o; o >>= 1) zsq += __shfl_xor_sync(0xffffffffu, zsq, o);
        if (lane == 0) {
            lossacc += zsq + bv_s[r];
            atomicAdd(&g_counts[k], 1.0f);
        }
    }
    if (lane == 0) atomicAdd(&g_loss, lossacc);
}

// ---------------------------------------------------------------------------
__global__ void k2_stats(const float* __restrict__ cs_in, float* __restrict__ out,
                         long long cs_off, long long loss_off) {
    __shared__ float red[KCODE];
    int t = threadIdx.x;
    float csn = cs_in[t] * DECAY + OMD * g_counts[t];
    out[cs_off + t] = csn;
    red[t] = csn;
    __syncthreads();
    for (int s = 512; s; s >>= 1) {
        if (t < s) red[t] += red[t + s];
        __syncthreads();
    }
    float n  = red[0];
    float cs = (csn + EPSV) / (n + (float)KCODE * EPSV) * n;
    g_invcs[t] = 1.0f / cs;
    if (t == 0) out[loss_off] = VQ_COMMIT * g_loss / (float)((long long)N_TOK * DDIM);
}

__global__ void k3_emb(const float* __restrict__ emean, float* __restrict__ out,
                       long long en_off, long long emn_off) {
    int i = blockIdx.x * blockDim.x + threadIdx.x;
    if (i >= KCODE * DDIM) return;
    int dd = i >> 10;
    int k  = i & 1023;
    float emn = emean[i] * DECAY + OMD * g_esum[(size_t)k * DDIM + dd];
    out[emn_off + i] = emn;
    out[en_off + i]  = emn * g_invcs[k];
}

// ---------------------------------------------------------------------------
extern "C" void kernel_launch(void* const* d_in, const int* in_sizes, int n_in,
                              void* d_out, int out_size) {
    const float* z  = (const float*)d_in[0];
    const float* E  = (const float*)d_in[1];
    const float* cs = (const float*)d_in[2];
    const float* em = (const float*)d_in[3];
    float* out = (float*)d_out;

    long long ND = in_sizes[0];
    long long DK = in_sizes[1];
    long long K  = in_sizes[2];
    long long loss_off = ND;
    long long en_off   = ND + 1;
    long long cs_off   = en_off + DK;
    long long emn_off  = cs_off + K;

    cudaFuncSetAttribute(k1_main, cudaFuncAttributeMaxDynamicSharedMemorySize, SMEM_K1);

    k0_prep<<<512, 256>>>(E);
    k0_enorm<<<128, 256>>>();
    // split: 296 CTAs (= 2 exact waves) + 216 CTAs (1.46 waves) — same total
    // wave count as one 512-CTA launch; gives ncu capture a shot at k1.
    k1_main<<<296, 512, SMEM_K1>>>(z, out, 0);
    k1_main<<<216, 512, SMEM_K1>>>(z, out, 296);
    k2_stats<<<1, 1024>>>(cs, out, cs_off, loss_off);
    k3_emb<<<(KCODE * DDIM + 255) / 256, 256>>>(em, out, en_off, emn_off);
}

// round 14
// speedup vs baseline: 1.5392x; 1.5392x over previous
#include <cuda_runtime.h>
#include <cuda_bf16.h>
#include <cstdint>

#define N_TOK   65536
#define DDIM    256
#define KCODE   1024
#define DECAY   0.99f
#define OMD     0.01f
#define EPSV    1e-5f
#define VQ_COMMIT 0.25f
#define TH_RES  0.8f

#define BM 128
#define APITCH 264          // bf16 elems per A smem row (pad for ldmatrix)

// smem byte offsets
#define SM_AH    0
#define A_SZ     (128 * APITCH * 2)                  // 67584
#define SM_ENORM A_SZ                                // 67584
#define SM_CANDV (SM_ENORM + 4096)                   // 71680: [128][8][3] float
#define SM_CANDI (SM_CANDV + 12288)                  // 83968: [128][8][3] int
#define SM_BV    (SM_CANDI + 12288)                  // 96256
#define SM_BI    (SM_BV + 512)                       // 96768
#define SM_FLAGN (SM_BI + 512)                       // 97280
#define SM_FLAGS (SM_FLAGN + 16)                     // 97296
#define SMEM_K1  (SM_FLAGS + 544)                    // 97840

// ---- device scratch ----
__device__ float g_Et[KCODE * DDIM];                 // [code][d] exact fp32
__device__ float g_esum[KCODE * DDIM];
__device__ float g_counts[KCODE];
__device__ float g_enorm[KCODE];
__device__ float g_invcs[KCODE];
__device__ float g_loss;
// B fragment-major, 16B-paired: [c(8)][wn(2)][s(16)][j2(4)][lane(32)] x 16B
__device__ __align__(16) unsigned char g_Bf[8 * 2 * 16 * 4 * 32 * 16];   // 512KB

// ---- PTX helpers ----
__device__ __forceinline__ uint32_t smem_u32(const void* p) {
    uint32_t a;
    asm("{ .reg .u64 t; cvta.to.shared.u64 t, %1; cvt.u32.u64 %0, t; }" : "=r"(a) : "l"(p));
    return a;
}
__device__ __forceinline__ void ldsm_x4(uint32_t* r, uint32_t a) {
    asm volatile("ldmatrix.sync.aligned.m8n8.x4.shared.b16 {%0,%1,%2,%3}, [%4];"
        : "=r"(r[0]), "=r"(r[1]), "=r"(r[2]), "=r"(r[3]) : "r"(a));
}
__device__ __forceinline__ void mma16816(float* d, const uint32_t* a, const uint32_t* b) {
    asm volatile("mma.sync.aligned.m16n8k16.row.col.f32.bf16.bf16.f32 "
        "{%0,%1,%2,%3}, {%4,%5,%6,%7}, {%8,%9}, {%0,%1,%2,%3};"
        : "+f"(d[0]), "+f"(d[1]), "+f"(d[2]), "+f"(d[3])
        : "r"(a[0]), "r"(a[1]), "r"(a[2]), "r"(a[3]), "r"(b[0]), "r"(b[1]));
}
__device__ __forceinline__ uint32_t pack_bf2(float x, float y) {
    __nv_bfloat16 a = __float2bfloat16(x), b = __float2bfloat16(y);
    return ((uint32_t)__bfloat16_as_ushort(b) << 16) | (uint32_t)__bfloat16_as_ushort(a);
}

// Reference-matching fp32 distance: strictly sequential FFMA chain over
// ascending d, then dist = fmaf(-2, dot, enorm).
__device__ __forceinline__ float chain_dist_f32(const float* __restrict__ zr,
                                                const float* __restrict__ er,
                                                float en) {
    float dot = 0.0f;
    #pragma unroll 16
    for (int i = 0; i < DDIM; ++i) {
        dot = fmaf(zr[i], er[i], dot);
    }
    return fmaf(-2.0f, dot, en);
}

// ---------------------------------------------------------------------------
// k0: exact Et [code][d], fragment-major 16B-paired bf16 B image, zero stats
// ---------------------------------------------------------------------------
__global__ void k0_prep(const float* __restrict__ E) {
    int stride = gridDim.x * blockDim.x;
    for (int i = blockIdx.x * blockDim.x + threadIdx.x; i < KCODE * DDIM; i += stride) {
        int k = i >> 8, dd = i & 255;   // code, dim
        float x = E[dd * KCODE + k];
        g_Et[i] = x;
        g_esum[i] = 0.0f;
        if (i < KCODE) g_counts[i] = 0.0f;
        if (i == 0)    g_loss = 0.0f;
        // fragment-major slot for mma.m16n8k16 B operand, (j,j+1) paired in 16B
        int c = k >> 7, nin = k & 127;
        int wn = nin >> 6, j = (nin >> 3) & 7, nrow = nin & 7;
        int s = dd >> 4, kin = dd & 15;
        int r = kin >> 3, kp = kin & 7, q = kp >> 1, bit = kp & 1;
        int l = nrow * 4 + q;
        int off = ((((c * 2 + wn) * 16 + s) * 4 + (j >> 1)) * 32 + l) * 16
                  + (j & 1) * 8 + r * 4 + bit * 2;
        *(__nv_bfloat16*)(g_Bf + off) = __float2bfloat16(x);
    }
}

__global__ void k0_enorm() {
    int gw = (blockIdx.x * blockDim.x + threadIdx.x) >> 5;
    int lane = threadIdx.x & 31;
    if (gw >= KCODE) return;
    const float4* row = (const float4*)(g_Et + (size_t)gw * DDIM);
    float s = 0.f;
    float4 a = row[lane];       s += a.x*a.x + a.y*a.y + a.z*a.z + a.w*a.w;
    float4 b = row[lane + 32];  s += b.x*b.x + b.y*b.y + b.z*b.z + b.w*b.w;
    #pragma unroll
    for (int o = 16; o; o >>= 1) s += __shfl_xor_sync(0xffffffffu, s, o);
    if (lane == 0) g_enorm[gw] = s;
}

// 3rd launch slot filler so k1 lands at launch position 4 (ncu capture slot)
__global__ void k_pad() { }

// ---------------------------------------------------------------------------
#define UPD3(v, ix, d, n) do { \
    if ((d) < (v)[0] || ((d) == (v)[0] && (n) < (ix)[0])) { \
        (v)[2]=(v)[1]; (ix)[2]=(ix)[1]; (v)[1]=(v)[0]; (ix)[1]=(ix)[0]; (v)[0]=(d); (ix)[0]=(n); \
    } else if ((d) < (v)[1] || ((d) == (v)[1] && (n) < (ix)[1])) { \
        (v)[2]=(v)[1]; (ix)[2]=(ix)[1]; (v)[1]=(d); (ix)[1]=(n); \
    } else if ((d) < (v)[2] || ((d) == (v)[2] && (n) < (ix)[2])) { \
        (v)[2]=(d); (ix)[2]=(n); \
    } } while (0)

// ---------------------------------------------------------------------------
// k1: 8-warp m32n64 hh HMMA GEMM, B streamed from fragment-major gmem with
//     manual double-buffer prefetch; per-lane top-3 + chain rescore + epilogue
// ---------------------------------------------------------------------------
__global__ __launch_bounds__(256, 2)
void k1_main(const float* __restrict__ z, float* __restrict__ out_zq) {
    extern __shared__ unsigned char sm[];
    const uint32_t sb = smem_u32(sm);
    float* en_s  = (float*)(sm + SM_ENORM);
    float* candv = (float*)(sm + SM_CANDV);
    int*   candi = (int*)(sm + SM_CANDI);
    float* bv_s  = (float*)(sm + SM_BV);
    int*   bi_s  = (int*)(sm + SM_BI);
    int*   flagn = (int*)(sm + SM_FLAGN);
    int*   flags = (int*)(sm + SM_FLAGS);

    const int tid = threadIdx.x, lane = tid & 31, wid = tid >> 5;
    const int wm = wid >> 1, wn = wid & 1;
    const int row0 = blockIdx.x * BM;

    if (tid == 0) *flagn = 0;

    // ---- A block load + bf16-hi into smem ----
    #pragma unroll 4
    for (int it = 0; it < 32; ++it) {
        int v = tid + it * 256;
        int r = v >> 6, c4 = v & 63;
        float4 x = *(const float4*)(z + (size_t)(row0 + r) * DDIM + c4 * 4);
        uint2 hh;
        hh.x = pack_bf2(x.x, x.y); hh.y = pack_bf2(x.z, x.w);
        *(uint2*)(sm + SM_AH + (size_t)(r * APITCH + c4 * 4) * 2) = hh;
    }
    *(float4*)(en_s + tid * 4) = *(const float4*)(g_enorm + tid * 4);
    __syncthreads();

    const uint32_t aAddr = sb + SM_AH +
        (uint32_t)(((wm * 32 + (lane & 15)) * APITCH + (lane >> 4) * 8) * 2);

    float tv[4][3];
    int   ti[4][3];
    #pragma unroll
    for (int g = 0; g < 4; ++g) { tv[g][0] = tv[g][1] = tv[g][2] = 3.4e38f; ti[g][0] = ti[g][1] = ti[g][2] = 0; }

    for (int c = 0; c < 8; ++c) {
        float acc[2][8][4];
        #pragma unroll
        for (int i = 0; i < 2; ++i)
            #pragma unroll
            for (int j = 0; j < 8; ++j)
                #pragma unroll
                for (int r = 0; r < 4; ++r) acc[i][j][r] = 0.f;

        const unsigned char* bc = g_Bf + (size_t)((c * 2 + wn) * 16) * 2048 + lane * 16;

        // prefetch s=0 B fragments
        uint4 bcur[4];
        {
            const uint4* bp = (const uint4*)bc;
            #pragma unroll
            for (int j2 = 0; j2 < 4; ++j2) bcur[j2] = bp[j2 * 32];
        }
        #pragma unroll
        for (int s = 0; s < 16; ++s) {
            // prefetch next s's B fragments before consuming current
            uint4 bnxt[4];
            if (s + 1 < 16) {
                const uint4* bp = (const uint4*)(bc + (s + 1) * 2048);
                #pragma unroll
                for (int j2 = 0; j2 < 4; ++j2) bnxt[j2] = bp[j2 * 32];
            }
            // A fragments from smem (two m16 halves of the m32 tile)
            uint32_t ah0[4], ah1[4];
            ldsm_x4(ah0, aAddr + (uint32_t)(s * 32));
            ldsm_x4(ah1, aAddr + (uint32_t)(s * 32) + 16 * APITCH * 2);
            #pragma unroll
            for (int j2 = 0; j2 < 4; ++j2) {
                const uint32_t* bw = (const uint32_t*)&bcur[j2];
                mma16816(acc[0][2 * j2],     ah0, bw);
                mma16816(acc[1][2 * j2],     ah1, bw);
                mma16816(acc[0][2 * j2 + 1], ah0, bw + 2);
                mma16816(acc[1][2 * j2 + 1], ah1, bw + 2);
            }
            #pragma unroll
            for (int j2 = 0; j2 < 4; ++j2) bcur[j2] = bnxt[j2];
        }

        // fold chunk c into per-lane top-3 (4 row-groups of the m32 tile)
        const int nb0 = c * 128 + wn * 64 + 2 * (lane & 3);
        #pragma unroll
        for (int j = 0; j < 8; ++j) {
            int n0 = nb0 + j * 8;
            float e0 = en_s[n0], e1 = en_s[n0 + 1];
            #pragma unroll
            for (int i = 0; i < 2; ++i) {
                float d0 = e0 - 2.0f * acc[i][j][0];
                float d1 = e1 - 2.0f * acc[i][j][1];
                float d2 = e0 - 2.0f * acc[i][j][2];
                float d3 = e1 - 2.0f * acc[i][j][3];
                UPD3(tv[i*2],   ti[i*2],   d0, n0);
                UPD3(tv[i*2],   ti[i*2],   d1, n0 + 1);
                UPD3(tv[i*2+1], ti[i*2+1], d2, n0);
                UPD3(tv[i*2+1], ti[i*2+1], d3, n0 + 1);
            }
        }
    }

    // ---- write all 24 per-row candidates (per-lane top-3, disjoint subsets) ----
    {
        const int lane8 = wn * 4 + (lane & 3);
        #pragma unroll
        for (int slot = 0; slot < 4; ++slot) {
            int row = wm * 32 + (slot >> 1) * 16 + (slot & 1) * 8 + (lane >> 2);
            int base = (row * 8 + lane8) * 3;
            candv[base + 0] = tv[slot][0]; candv[base + 1] = tv[slot][1]; candv[base + 2] = tv[slot][2];
            candi[base + 0] = ti[slot][0]; candi[base + 1] = ti[slot][1]; candi[base + 2] = ti[slot][2];
        }
    }
    __syncthreads();

    // ---- per-row finalize (threads 0..127) ----
    if (tid < 128) {
        const int base = tid * 24;
        float v0 = candv[base]; int i0 = candi[base];
        #pragma unroll
        for (int t = 1; t < 24; ++t) {
            float v = candv[base + t]; int i = candi[base + t];
            if (v < v0 || (v == v0 && i < i0)) { v0 = v; i0 = i; }
        }
        // safety net: min over lanes of each lane's 3rd-best
        float m3 = candv[base + 2];
        #pragma unroll
        for (int L = 1; L < 8; ++L) m3 = fminf(m3, candv[base + L * 3 + 2]);

        // gather candidates within TH of best
        int cl[8]; int cnt = 0;
        #pragma unroll
        for (int t = 0; t < 24; ++t) {
            if (candv[base + t] < v0 + TH_RES) {
                if (cnt < 8) cl[cnt] = candi[base + t];
                ++cnt;
            }
        }

        if (m3 < v0 + TH_RES || cnt > 8) {
            int s = atomicAdd(flagn, 1);
            flags[s] = tid;                      // full chain-fp32 rescan later
            bv_s[tid] = v0; bi_s[tid] = i0;      // placeholder (overwritten)
        } else if (cnt <= 1) {
            bv_s[tid] = v0; bi_s[tid] = i0;
        } else {
            const float* zr = z + (size_t)(row0 + tid) * DDIM;
            float bd = 3.4e38f; int bk = 0x7fffffff;
            for (int t = 0; t < cnt; ++t) {
                int k = cl[t];
                float d = chain_dist_f32(zr, g_Et + (size_t)k * DDIM, en_s[k]);
                if (d < bd || (d == bd && k < bk)) { bd = d; bk = k; }
            }
            bv_s[tid] = bd; bi_s[tid] = bk;
        }
    }
    __syncthreads();

    // ---- rare full chain-fp32 rescan (warp-cooperative) ----
    int nf = *flagn;
    for (int f = wid; f < nf; f += 8) {
        int row = flags[f];
        const float* zr = z + (size_t)(row0 + row) * DDIM;
        float bd = 3.4e38f; int bk = 0x7fffffff;
        for (int k = lane; k < KCODE; k += 32) {
            float d = chain_dist_f32(zr, g_Et + (size_t)k * DDIM, en_s[k]);
            if (d < bd) { bd = d; bk = k; }
        }
        #pragma unroll
        for (int o = 16; o; o >>= 1) {
            float ov = __shfl_xor_sync(0xffffffffu, bd, o);
            int   ok = __shfl_xor_sync(0xffffffffu, bk, o);
            if (ov < bd || (ov == bd && ok < bk)) { bd = ov; bk = ok; }
        }
        if (lane == 0) { bv_s[row] = bd; bi_s[row] = bk; }
    }
    __syncthreads();

    // ---- fused epilogue: 8 warps x 16 rows ----
    float lossacc = 0.f;
    #pragma unroll
    for (int rr = 0; rr < 16; ++rr) {
        int r = wid * 16 + rr;
        int R = row0 + r;
        int k = bi_s[r];
        const float4* zrow = (const float4*)(z + (size_t)R * DDIM);
        float4*       orow = (float4*)(out_zq + (size_t)R * DDIM);
        const float4* et   = (const float4*)(g_Et + (size_t)k * DDIM);
        float zsq = 0.f;
        #pragma unroll
        for (int itc = 0; itc < 2; ++itc) {
            int cidx = lane + itc * 32;
            float4 zv = zrow[cidx];
            zsq += zv.x * zv.x + zv.y * zv.y + zv.z * zv.z + zv.w * zv.w;
            float* es = g_esum + (size_t)k * DDIM + cidx * 4;
            atomicAdd(es + 0, zv.x);
            atomicAdd(es + 1, zv.y);
            atomicAdd(es + 2, zv.z);
            atomicAdd(es + 3, zv.w);
            orow[cidx] = et[cidx];
        }
        #pragma unroll
        for (int o = 16; o; o >>= 1) zsq += __shfl_xor_sync(0xffffffffu, zsq, o);
        if (lane == 0) {
            lossacc += zsq + bv_s[r];
            atomicAdd(&g_counts[k], 1.0f);
        }
    }
    if (lane == 0) atomicAdd(&g_loss, lossacc);
}

// ---------------------------------------------------------------------------
__global__ void k2_stats(const float* __restrict__ cs_in, float* __restrict__ out,
                         long long cs_off, long long loss_off) {
    __shared__ float red[KCODE];
    int t = threadIdx.x;
    float csn = cs_in[t] * DECAY + OMD * g_counts[t];
    out[cs_off + t] = csn;
    red[t] = csn;
    __syncthreads();
    for (int s = 512; s; s >>= 1) {
        if (t < s) red[t] += red[t + s];
        __syncthreads();
    }
    float n  = red[0];
    float cs = (csn + EPSV) / (n + (float)KCODE * EPSV) * n;
    g_invcs[t] = 1.0f / cs;
    if (t == 0) out[loss_off] = VQ_COMMIT * g_loss / (float)((long long)N_TOK * DDIM);
}

__global__ void k3_emb(const float* __restrict__ emean, float* __restrict__ out,
                       long long en_off, long long emn_off) {
    int i = blockIdx.x * blockDim.x + threadIdx.x;
    if (i >= KCODE * DDIM) return;
    int dd = i >> 10;
    int k  = i & 1023;
    float emn = emean[i] * DECAY + OMD * g_esum[(size_t)k * DDIM + dd];
    out[emn_off + i] = emn;
    out[en_off + i]  = emn * g_invcs[k];
}

// ---------------------------------------------------------------------------
extern "C" void kernel_launch(void* const* d_in, const int* in_sizes, int n_in,
                              void* d_out, int out_size) {
    const float* z  = (const float*)d_in[0];
    const float* E  = (const float*)d_in[1];
    const float* cs = (const float*)d_in[2];
    const float* em = (const float*)d_in[3];
    float* out = (float*)d_out;

    long long ND = in_sizes[0];
    long long DK = in_sizes[1];
    long long K  = in_sizes[2];
    long long loss_off = ND;
    long long en_off   = ND + 1;
    long long cs_off   = en_off + DK;
    long long emn_off  = cs_off + K;

    cudaFuncSetAttribute(k1_main, cudaFuncAttributeMaxDynamicSharedMemorySize, SMEM_K1);

    k0_prep<<<512, 256>>>(E);          // launch 1
    k0_enorm<<<128, 256>>>();          // launch 2
    k_pad<<<1, 32>>>();                // launch 3 (positions k1 at slot 4 for ncu)
    k1_main<<<N_TOK / BM, 256, SMEM_K1>>>(z, out);   // launch 4 — profiled
    k2_stats<<<1, 1024>>>(cs, out, cs_off, loss_off);
    k3_emb<<<(KCODE * DDIM + 255) / 256, 256>>>(em, out, en_off, emn_off);
}

// round 15
// speedup vs baseline: 1.6023x; 1.0410x over previous
#include <cuda_runtime.h>
#include <cuda_bf16.h>
#include <cstdint>

#define N_TOK   65536
#define DDIM    256
#define KCODE   1024
#define DECAY   0.99f
#define OMD     0.01f
#define EPSV    1e-5f
#define VQ_COMMIT 0.25f
#define TH_RES  0.8f

#define BM 128
#define APITCH 264          // bf16 elems per A smem row (pad for ldmatrix)

// smem byte offsets
#define SM_AH    0
#define A_SZ     (128 * APITCH * 2)                  // 67584
#define SM_ENORM A_SZ                                // 67584
#define SM_CANDV (SM_ENORM + 4096)                   // 71680: [128][8][3] float
#define SM_CANDI (SM_CANDV + 12288)                  // 83968: [128][8][3] int
#define SM_BV    (SM_CANDI + 12288)                  // 96256
#define SM_BI    (SM_BV + 512)                       // 96768
#define SM_FLAGN (SM_BI + 512)                       // 97280
#define SM_FLAGS (SM_FLAGN + 16)                     // 97296
#define SMEM_K1  (SM_FLAGS + 544)                    // 97840

// ---- device scratch ----
__device__ float g_Et[KCODE * DDIM];                 // [code][d] exact fp32
__device__ float g_esum[KCODE * DDIM];
__device__ float g_counts[KCODE];
__device__ float g_enorm[KCODE];
__device__ float g_invcs[KCODE];
__device__ float g_loss;
// B fragment-major, 16B-paired: [c(16)][wn(2)][s(16)][j2(2)][lane(32)] x 16B
__device__ __align__(16) unsigned char g_Bf[16 * 2 * 16 * 2 * 32 * 16];  // 512KB

// ---- PTX helpers ----
__device__ __forceinline__ uint32_t smem_u32(const void* p) {
    uint32_t a;
    asm("{ .reg .u64 t; cvta.to.shared.u64 t, %1; cvt.u32.u64 %0, t; }" : "=r"(a) : "l"(p));
    return a;
}
__device__ __forceinline__ void ldsm_x4(uint32_t* r, uint32_t a) {
    asm volatile("ldmatrix.sync.aligned.m8n8.x4.shared.b16 {%0,%1,%2,%3}, [%4];"
        : "=r"(r[0]), "=r"(r[1]), "=r"(r[2]), "=r"(r[3]) : "r"(a));
}
__device__ __forceinline__ void mma16816(float* d, const uint32_t* a, const uint32_t* b) {
    asm volatile("mma.sync.aligned.m16n8k16.row.col.f32.bf16.bf16.f32 "
        "{%0,%1,%2,%3}, {%4,%5,%6,%7}, {%8,%9}, {%0,%1,%2,%3};"
        : "+f"(d[0]), "+f"(d[1]), "+f"(d[2]), "+f"(d[3])
        : "r"(a[0]), "r"(a[1]), "r"(a[2]), "r"(a[3]), "r"(b[0]), "r"(b[1]));
}
__device__ __forceinline__ uint32_t pack_bf2(float x, float y) {
    __nv_bfloat16 a = __float2bfloat16(x), b = __float2bfloat16(y);
    return ((uint32_t)__bfloat16_as_ushort(b) << 16) | (uint32_t)__bfloat16_as_ushort(a);
}

// Reference-matching fp32 distance: strictly sequential FFMA chain over
// ascending d, then dist = fmaf(-2, dot, enorm).
__device__ __forceinline__ float chain_dist_f32(const float* __restrict__ zr,
                                                const float* __restrict__ er,
                                                float en) {
    float dot = 0.0f;
    #pragma unroll 16
    for (int i = 0; i < DDIM; ++i) {
        dot = fmaf(zr[i], er[i], dot);
    }
    return fmaf(-2.0f, dot, en);
}

// ---------------------------------------------------------------------------
// k0: exact Et [code][d], fragment-major 16B-paired bf16 B image, zero stats
// ---------------------------------------------------------------------------
__global__ void k0_prep(const float* __restrict__ E) {
    int stride = gridDim.x * blockDim.x;
    for (int i = blockIdx.x * blockDim.x + threadIdx.x; i < KCODE * DDIM; i += stride) {
        int k = i >> 8, dd = i & 255;   // code, dim
        float x = E[dd * KCODE + k];
        g_Et[i] = x;
        g_esum[i] = 0.0f;
        if (i < KCODE) g_counts[i] = 0.0f;
        if (i == 0)    g_loss = 0.0f;
        // fragment-major slot for mma.m16n8k16 B operand, (j,j+1) paired in 16B
        int c = k >> 6, nin = k & 63;
        int wn = nin >> 5, nin2 = nin & 31;
        int j = nin2 >> 3, nrow = nin2 & 7;
        int s = dd >> 4, kin = dd & 15;
        int r = kin >> 3, kp = kin & 7, q = kp >> 1, bit = kp & 1;
        int l = nrow * 4 + q;
        int off = ((((c * 2 + wn) * 16 + s) * 2 + (j >> 1)) * 32 + l) * 16
                  + (j & 1) * 8 + r * 4 + bit * 2;
        *(__nv_bfloat16*)(g_Bf + off) = __float2bfloat16(x);
    }
}

__global__ void k0_enorm() {
    int gw = (blockIdx.x * blockDim.x + threadIdx.x) >> 5;
    int lane = threadIdx.x & 31;
    if (gw >= KCODE) return;
    const float4* row = (const float4*)(g_Et + (size_t)gw * DDIM);
    float s = 0.f;
    float4 a = row[lane];       s += a.x*a.x + a.y*a.y + a.z*a.z + a.w*a.w;
    float4 b = row[lane + 32];  s += b.x*b.x + b.y*b.y + b.z*b.z + b.w*b.w;
    #pragma unroll
    for (int o = 16; o; o >>= 1) s += __shfl_xor_sync(0xffffffffu, s, o);
    if (lane == 0) g_enorm[gw] = s;
}

// 3rd launch slot filler so k1 lands at launch position 4 (ncu capture slot)
__global__ void k_pad() { }

// ---------------------------------------------------------------------------
#define UPD3(v, ix, d, n) do { \
    if ((d) < (v)[0] || ((d) == (v)[0] && (n) < (ix)[0])) { \
        (v)[2]=(v)[1]; (ix)[2]=(ix)[1]; (v)[1]=(v)[0]; (ix)[1]=(ix)[0]; (v)[0]=(d); (ix)[0]=(n); \
    } else if ((d) < (v)[1] || ((d) == (v)[1] && (n) < (ix)[1])) { \
        (v)[2]=(v)[1]; (ix)[2]=(ix)[1]; (v)[1]=(d); (ix)[1]=(n); \
    } else if ((d) < (v)[2] || ((d) == (v)[2] && (n) < (ix)[2])) { \
        (v)[2]=(d); (ix)[2]=(n); \
    } } while (0)

// ---------------------------------------------------------------------------
// k1: 8-warp m32n32 hh HMMA GEMM, B streamed from fragment-major gmem with
//     depth-2 prefetch; per-lane top-3 + chain-fp32 rescore + fused epilogue
// ---------------------------------------------------------------------------
__global__ __launch_bounds__(256, 2)
void k1_main(const float* __restrict__ z, float* __restrict__ out_zq) {
    extern __shared__ unsigned char sm[];
    const uint32_t sb = smem_u32(sm);
    float* en_s  = (float*)(sm + SM_ENORM);
    float* candv = (float*)(sm + SM_CANDV);
    int*   candi = (int*)(sm + SM_CANDI);
    float* bv_s  = (float*)(sm + SM_BV);
    int*   bi_s  = (int*)(sm + SM_BI);
    int*   flagn = (int*)(sm + SM_FLAGN);
    int*   flags = (int*)(sm + SM_FLAGS);

    const int tid = threadIdx.x, lane = tid & 31, wid = tid >> 5;
    const int wm = wid >> 1, wn = wid & 1;
    const int row0 = blockIdx.x * BM;

    if (tid == 0) *flagn = 0;

    // ---- A block load + bf16-hi into smem ----
    #pragma unroll 4
    for (int it = 0; it < 32; ++it) {
        int v = tid + it * 256;
        int r = v >> 6, c4 = v & 63;
        float4 x = *(const float4*)(z + (size_t)(row0 + r) * DDIM + c4 * 4);
        uint2 hh;
        hh.x = pack_bf2(x.x, x.y); hh.y = pack_bf2(x.z, x.w);
        *(uint2*)(sm + SM_AH + (size_t)(r * APITCH + c4 * 4) * 2) = hh;
    }
    *(float4*)(en_s + tid * 4) = *(const float4*)(g_enorm + tid * 4);
    __syncthreads();

    const uint32_t aAddr = sb + SM_AH +
        (uint32_t)(((wm * 32 + (lane & 15)) * APITCH + (lane >> 4) * 8) * 2);

    float tv[4][3];
    int   ti[4][3];
    #pragma unroll
    for (int g = 0; g < 4; ++g) { tv[g][0] = tv[g][1] = tv[g][2] = 3.4e38f; ti[g][0] = ti[g][1] = ti[g][2] = 0; }

    for (int c = 0; c < 16; ++c) {
        float acc[2][4][4];
        #pragma unroll
        for (int i = 0; i < 2; ++i)
            #pragma unroll
            for (int j = 0; j < 4; ++j)
                #pragma unroll
                for (int r = 0; r < 4; ++r) acc[i][j][r] = 0.f;

        // per s-step stride: 2 j2-slots x 512B = 1024B
        const unsigned char* bc = g_Bf + (size_t)((c * 2 + wn) * 16) * 1024 + lane * 16;

        // depth-2 rotating prefetch buffers
        uint4 bufs[3][2];
        {
            const uint4* p0 = (const uint4*)bc;
            const uint4* p1 = (const uint4*)(bc + 1024);
            bufs[0][0] = p0[0];  bufs[0][1] = p0[32];
            bufs[1][0] = p1[0];  bufs[1][1] = p1[32];
        }
        #pragma unroll
        for (int s = 0; s < 16; ++s) {
            if (s + 2 < 16) {
                const uint4* pn = (const uint4*)(bc + (s + 2) * 1024);
                bufs[(s + 2) % 3][0] = pn[0];
                bufs[(s + 2) % 3][1] = pn[32];
            }
            uint32_t ah0[4], ah1[4];
            ldsm_x4(ah0, aAddr + (uint32_t)(s * 32));
            ldsm_x4(ah1, aAddr + (uint32_t)(s * 32) + 16 * APITCH * 2);
            #pragma unroll
            for (int j2 = 0; j2 < 2; ++j2) {
                const uint32_t* bw = (const uint32_t*)&bufs[s % 3][j2];
                mma16816(acc[0][2 * j2],     ah0, bw);
                mma16816(acc[1][2 * j2],     ah1, bw);
                mma16816(acc[0][2 * j2 + 1], ah0, bw + 2);
                mma16816(acc[1][2 * j2 + 1], ah1, bw + 2);
            }
        }

        // fold chunk c (64 codes) into per-lane top-3 (4 row-groups)
        const int nb0 = c * 64 + wn * 32 + 2 * (lane & 3);
        #pragma unroll
        for (int j = 0; j < 4; ++j) {
            int n0 = nb0 + j * 8;
            float e0 = en_s[n0], e1 = en_s[n0 + 1];
            #pragma unroll
            for (int i = 0; i < 2; ++i) {
                float d0 = e0 - 2.0f * acc[i][j][0];
                float d1 = e1 - 2.0f * acc[i][j][1];
                float d2 = e0 - 2.0f * acc[i][j][2];
                float d3 = e1 - 2.0f * acc[i][j][3];
                UPD3(tv[i*2],   ti[i*2],   d0, n0);
                UPD3(tv[i*2],   ti[i*2],   d1, n0 + 1);
                UPD3(tv[i*2+1], ti[i*2+1], d2, n0);
                UPD3(tv[i*2+1], ti[i*2+1], d3, n0 + 1);
            }
        }
    }

    // ---- write all 24 per-row candidates (per-lane top-3, disjoint subsets) ----
    {
        const int lane8 = wn * 4 + (lane & 3);
        #pragma unroll
        for (int slot = 0; slot < 4; ++slot) {
            int row = wm * 32 + (slot >> 1) * 16 + (slot & 1) * 8 + (lane >> 2);
            int base = (row * 8 + lane8) * 3;
            candv[base + 0] = tv[slot][0]; candv[base + 1] = tv[slot][1]; candv[base + 2] = tv[slot][2];
            candi[base + 0] = ti[slot][0]; candi[base + 1] = ti[slot][1]; candi[base + 2] = ti[slot][2];
        }
    }
    __syncthreads();

    // ---- per-row finalize (threads 0..127) ----
    if (tid < 128) {
        const int base = tid * 24;
        float v0 = candv[base]; int i0 = candi[base];
        #pragma unroll
        for (int t = 1; t < 24; ++t) {
            float v = candv[base + t]; int i = candi[base + t];
            if (v < v0 || (v == v0 && i < i0)) { v0 = v; i0 = i; }
        }
        // safety net: min over lanes of each lane's 3rd-best
        float m3 = candv[base + 2];
        #pragma unroll
        for (int L = 1; L < 8; ++L) m3 = fminf(m3, candv[base + L * 3 + 2]);

        // gather candidates within TH of best
        int cl[8]; int cnt = 0;
        #pragma unroll
        for (int t = 0; t < 24; ++t) {
            if (candv[base + t] < v0 + TH_RES) {
                if (cnt < 8) cl[cnt] = candi[base + t];
                ++cnt;
            }
        }

        if (m3 < v0 + TH_RES || cnt > 8) {
            int s = atomicAdd(flagn, 1);
            flags[s] = tid;                      // full chain-fp32 rescan later
            bv_s[tid] = v0; bi_s[tid] = i0;      // placeholder (overwritten)
        } else if (cnt <= 1) {
            bv_s[tid] = v0; bi_s[tid] = i0;
        } else {
            const float* zr = z + (size_t)(row0 + tid) * DDIM;
            float bd = 3.4e38f; int bk = 0x7fffffff;
            for (int t = 0; t < cnt; ++t) {
                int k = cl[t];
                float d = chain_dist_f32(zr, g_Et + (size_t)k * DDIM, en_s[k]);
                if (d < bd || (d == bd && k < bk)) { bd = d; bk = k; }
            }
            bv_s[tid] = bd; bi_s[tid] = bk;
        }
    }
    __syncthreads();

    // ---- rare full chain-fp32 rescan (warp-cooperative) ----
    int nf = *flagn;
    for (int f = wid; f < nf; f += 8) {
        int row = flags[f];
        const float* zr = z + (size_t)(row0 + row) * DDIM;
        float bd = 3.4e38f; int bk = 0x7fffffff;
        for (int k = lane; k < KCODE; k += 32) {
            float d = chain_dist_f32(zr, g_Et + (size_t)k * DDIM, en_s[k]);
            if (d < bd) { bd = d; bk = k; }
        }
        #pragma unroll
        for (int o = 16; o; o >>= 1) {
            float ov = __shfl_xor_sync(0xffffffffu, bd, o);
            int   ok = __shfl_xor_sync(0xffffffffu, bk, o);
            if (ov < bd || (ov == bd && ok < bk)) { bd = ov; bk = ok; }
        }
        if (lane == 0) { bv_s[row] = bd; bi_s[row] = bk; }
    }
    __syncthreads();

    // ---- fused epilogue: 8 warps x 16 rows ----
    float lossacc = 0.f;
    #pragma unroll
    for (int rr = 0; rr < 16; ++rr) {
        int r = wid * 16 + rr;
        int R = row0 + r;
        int k = bi_s[r];
        const float4* zrow = (const float4*)(z + (size_t)R * DDIM);
        float4*       orow = (float4*)(out_zq + (size_t)R * DDIM);
        const float4* et   = (const float4*)(g_Et + (size_t)k * DDIM);
        float zsq = 0.f;
        #pragma unroll
        for (int itc = 0; itc < 2; ++itc) {
            int cidx = lane + itc * 32;
            float4 zv = zrow[cidx];
            zsq += zv.x * zv.x + zv.y * zv.y + zv.z * zv.z + zv.w * zv.w;
            float* es = g_esum + (size_t)k * DDIM + cidx * 4;
            atomicAdd(es + 0, zv.x);
            atomicAdd(es + 1, zv.y);
            atomicAdd(es + 2, zv.z);
            atomicAdd(es + 3, zv.w);
            orow[cidx] = et[cidx];
        }
        #pragma unroll
        for (int o = 16; o; o >>= 1) zsq += __shfl_xor_sync(0xffffffffu, zsq, o);
        if (lane == 0) {
            lossacc += zsq + bv_s[r];
            atomicAdd(&g_counts[k], 1.0f);
        }
    }
    if (lane == 0) atomicAdd(&g_loss, lossacc);
}

// ---------------------------------------------------------------------------
__global__ void k2_stats(const float* __restrict__ cs_in, float* __restrict__ out,
                         long long cs_off, long long loss_off) {
    __shared__ float red[KCODE];
    int t = threadIdx.x;
    float csn = cs_in[t] * DECAY + OMD * g_counts[t];
    out[cs_off + t] = csn;
    red[t] = csn;
    __syncthreads();
    for (int s = 512; s; s >>= 1) {
        if (t < s) red[t] += red[t + s];
        __syncthreads();
    }
    float n  = red[0];
    float cs = (csn + EPSV) / (n + (float)KCODE * EPSV) * n;
    g_invcs[t] = 1.0f / cs;
    if (t == 0) out[loss_off] = VQ_COMMIT * g_loss / (float)((long long)N_TOK * DDIM);
}

__global__ void k3_emb(const float* __restrict__ emean, float* __restrict__ out,
                       long long en_off, long long emn_off) {
    int i = blockIdx.x * blockDim.x + threadIdx.x;
    if (i >= KCODE * DDIM) return;
    int dd = i >> 10;
    int k  = i & 1023;
    float emn = emean[i] * DECAY + OMD * g_esum[(size_t)k * DDIM + dd];
    out[emn_off + i] = emn;
    out[en_off + i]  = emn * g_invcs[k];
}

// ---------------------------------------------------------------------------
extern "C" void kernel_launch(void* const* d_in, const int* in_sizes, int n_in,
                              void* d_out, int out_size) {
    const float* z  = (const float*)d_in[0];
    const float* E  = (const float*)d_in[1];
    const float* cs = (const float*)d_in[2];
    const float* em = (const float*)d_in[3];
    float* out = (float*)d_out;

    long long ND = in_sizes[0];
    long long DK = in_sizes[1];
    long long K  = in_sizes[2];
    long long loss_off = ND;
    long long en_off   = ND + 1;
    long long cs_off   = en_off + DK;
    long long emn_off  = cs_off + K;

    cudaFuncSetAttribute(k1_main, cudaFuncAttributeMaxDynamicSharedMemorySize, SMEM_K1);

    k0_prep<<<512, 256>>>(E);          // launch 1
    k0_enorm<<<128, 256>>>();          // launch 2
    k_pad<<<1, 32>>>();                // launch 3 (positions k1 at slot 4 for ncu)
    k1_main<<<N_TOK / BM, 256, SMEM_K1>>>(z, out);   // launch 4 — profiled
    k2_stats<<<1, 1024>>>(cs, out, cs_off, loss_off);
    k3_emb<<<(KCODE * DDIM + 255) / 256, 256>>>(em, out, en_off, emn_off);
}